// round 1
// baseline (speedup 1.0000x reference)
#include <cuda_runtime.h>

typedef unsigned long long ull;

#define NWARPS 8
// per-warp smem floats:
//  sS  : 2*168  = 336   @ 0
//  sHT : 2*576  = 1152  @ 336    (H transposed, row stride 9: [i*9+n])
//  sHP : 2*1056 = 2112  @ 1488   (hp: [n*132 + h*33 + d])
//  sWD : 2*132  = 264   @ 3600   (w_dvd: [h*33 + d])
//  sAD : 16             @ 3864   (adv_q per row)
#define WARP_FLOATS 3880

__device__ __forceinline__ ull pk2(float x, float y) {
    ull r; asm("mov.b64 %0, {%1, %2};" : "=l"(r) : "f"(x), "f"(y)); return r;
}
__device__ __forceinline__ ull dup2(float x) {
    ull r; asm("mov.b64 %0, {%1, %1};" : "=l"(r) : "f"(x)); return r;
}
__device__ __forceinline__ void fma2(ull& d, ull a, ull b) {
    asm("fma.rn.f32x2 %0, %1, %2, %0;" : "+l"(d) : "l"(a), "l"(b));
}
__device__ __forceinline__ float2 up2(ull v) {
    float2 f; asm("mov.b64 {%0, %1}, %2;" : "=f"(f.x), "=f"(f.y) : "l"(v)); return f;
}

__global__ void __launch_bounds__(NWARPS * 32, 1)
dvd_kernel(float* __restrict__ out,
           const float* __restrict__ Qv,  const float* __restrict__ Sg,
           const float* __restrict__ MQ,  const float* __restrict__ Hg,
           const float* __restrict__ w1f, const float* __restrict__ b1f,
           const float* __restrict__ w2f, const float* __restrict__ b2f,
           const float* __restrict__ Wg,  const float* __restrict__ attA,
           const float* __restrict__ Wd,  const float* __restrict__ bd,
           int B)
{
    extern __shared__ float sm[];
    const int l  = threadIdx.x & 31;
    const int wz = threadIdx.x >> 5;
    float* wb = sm + wz * WARP_FLOATS;

    const int base = (blockIdx.x * NWARPS + wz) * 2;
    if (base >= B) return;
    const int r0  = base;
    const bool v1 = (base + 1) < B;
    const int r1  = v1 ? (base + 1) : r0;

    float* sS0 = wb;          float* sS1 = wb + 168;
    float* sT0 = wb + 336;    float* sT1 = sT0 + 576;
    float* sP0 = wb + 1488;   float* sP1 = sP0 + 1056;
    float* sW0 = wb + 3600;   float* sW1 = sW0 + 132;
    float* sA0 = wb + 3864;   float* sA1 = sA0 + 8;

    // ---------------- Phase A: stage S and transposed H ----------------
    {
        const float* s0p = Sg + (size_t)r0 * 168;
        const float* s1p = Sg + (size_t)r1 * 168;
        for (int t = l; t < 168; t += 32) { sS0[t] = s0p[t]; sS1[t] = s1p[t]; }
        const float* h0p = Hg + (size_t)r0 * 512;
        const float* h1p = Hg + (size_t)r1 * 512;
        #pragma unroll
        for (int c = 0; c < 16; c++) {
            int t = c * 32 + l;
            int n = t >> 6, i = t & 63;
            sT0[i * 9 + n] = h0p[t];
            sT1[i * 9 + n] = h1p[t];
        }
    }
    __syncwarp();

    // ---------------- Phase B: h1f = relu(S@w1f+b1f); w_final; adv_q ----------------
    {
        ull a0 = pk2(b1f[2 * l], b1f[2 * l + 1]);
        ull a1 = a0;
        #pragma unroll 8
        for (int k = 0; k < 168; k++) {
            float2 wv = *reinterpret_cast<const float2*>(w1f + k * 64 + 2 * l);
            ull wp = pk2(wv.x, wv.y);
            fma2(a0, dup2(sS0[k]), wp);
            fma2(a1, dup2(sS1[k]), wp);
        }
        float2 f0 = up2(a0), f1 = up2(a1);
        f0.x = fmaxf(f0.x, 0.f); f0.y = fmaxf(f0.y, 0.f);
        f1.x = fmaxf(f1.x, 0.f); f1.y = fmaxf(f1.y, 0.f);

        float4 wa0 = __ldg((const float4*)(w2f + (2 * l) * 8));
        float4 wa1 = __ldg((const float4*)(w2f + (2 * l) * 8 + 4));
        float4 wb0 = __ldg((const float4*)(w2f + (2 * l + 1) * 8));
        float4 wb1 = __ldg((const float4*)(w2f + (2 * l + 1) * 8 + 4));
        float wa[8]  = {wa0.x, wa0.y, wa0.z, wa0.w, wa1.x, wa1.y, wa1.z, wa1.w};
        float wbv[8] = {wb0.x, wb0.y, wb0.z, wb0.w, wb1.x, wb1.y, wb1.z, wb1.w};

        float p0[8], p1[8];
        #pragma unroll
        for (int a = 0; a < 8; a++) {
            p0[a] = f0.x * wa[a] + f0.y * wbv[a];
            p1[a] = f1.x * wa[a] + f1.y * wbv[a];
        }
        #pragma unroll
        for (int off = 16; off >= 1; off >>= 1) {
            #pragma unroll
            for (int a = 0; a < 8; a++) {
                p0[a] += __shfl_xor_sync(0xffffffffu, p0[a], off);
                p1[a] += __shfl_xor_sync(0xffffffffu, p1[a], off);
            }
        }
        if (l == 0) {
            float4 qa = __ldg((const float4*)(Qv + (size_t)r0 * 8));
            float4 qb = __ldg((const float4*)(Qv + (size_t)r0 * 8 + 4));
            float4 ma = __ldg((const float4*)(MQ + (size_t)r0 * 8));
            float4 mb = __ldg((const float4*)(MQ + (size_t)r0 * 8 + 4));
            float qd[8] = {qa.x - ma.x, qa.y - ma.y, qa.z - ma.z, qa.w - ma.w,
                           qb.x - mb.x, qb.y - mb.y, qb.z - mb.z, qb.w - mb.w};
            #pragma unroll
            for (int a = 0; a < 8; a++) {
                float wf = fabsf(p0[a] + b2f[a]) + 1e-10f;
                sA0[a] = wf * qd[a];
            }
            float4 qa1 = __ldg((const float4*)(Qv + (size_t)r1 * 8));
            float4 qb1 = __ldg((const float4*)(Qv + (size_t)r1 * 8 + 4));
            float4 ma1 = __ldg((const float4*)(MQ + (size_t)r1 * 8));
            float4 mb1 = __ldg((const float4*)(MQ + (size_t)r1 * 8 + 4));
            float qd1[8] = {qa1.x - ma1.x, qa1.y - ma1.y, qa1.z - ma1.z, qa1.w - ma1.w,
                            qb1.x - mb1.x, qb1.y - mb1.y, qb1.z - mb1.z, qb1.w - mb1.w};
            #pragma unroll
            for (int a = 0; a < 8; a++) {
                float wf = fabsf(p1[a] + b2f[a]) + 1e-10f;
                sA1[a] = wf * qd1[a];
            }
        }
    }

    // ---------------- Phase C: w_dvd = S@Wd + bd ----------------
    {
        float4 b4 = __ldg((const float4*)(bd + 4 * l));
        ull c00 = pk2(b4.x, b4.y), c01 = pk2(b4.z, b4.w);
        ull c10 = c00, c11 = c01;
        #pragma unroll 4
        for (int k = 0; k < 168; k++) {
            float4 wv = __ldg((const float4*)(Wd + k * 128 + 4 * l));
            ull wp0 = pk2(wv.x, wv.y), wp1 = pk2(wv.z, wv.w);
            ull s0 = dup2(sS0[k]), s1 = dup2(sS1[k]);
            fma2(c00, s0, wp0); fma2(c01, s0, wp1);
            fma2(c10, s1, wp0); fma2(c11, s1, wp1);
        }
        const int hh = l >> 3, dd = 4 * (l & 7);
        float2 x0 = up2(c00), x1 = up2(c01);
        float* p = sW0 + hh * 33 + dd;
        p[0] = x0.x; p[1] = x0.y; p[2] = x1.x; p[3] = x1.y;
        x0 = up2(c10); x1 = up2(c11);
        p = sW1 + hh * 33 + dd;
        p[0] = x0.x; p[1] = x0.y; p[2] = x1.x; p[3] = x1.y;
    }

    // ---------------- Phase D: hp = H @ Wg (8x64 @ 64x128), reg accum ----------------
    {
        ull acc0[8][2], acc1[8][2];
        #pragma unroll
        for (int n = 0; n < 8; n++) {
            acc0[n][0] = 0ull; acc0[n][1] = 0ull;
            acc1[n][0] = 0ull; acc1[n][1] = 0ull;
        }
        #pragma unroll 2
        for (int i = 0; i < 64; i++) {
            float4 wg = __ldg((const float4*)(Wg + i * 128 + 4 * l));
            ull wp0 = pk2(wg.x, wg.y), wp1 = pk2(wg.z, wg.w);
            #pragma unroll
            for (int n = 0; n < 8; n++) {
                ull h0 = dup2(sT0[i * 9 + n]);
                fma2(acc0[n][0], h0, wp0); fma2(acc0[n][1], h0, wp1);
                ull h1 = dup2(sT1[i * 9 + n]);
                fma2(acc1[n][0], h1, wp0); fma2(acc1[n][1], h1, wp1);
            }
        }
        const int hh = l >> 3, dd = 4 * (l & 7);
        #pragma unroll
        for (int n = 0; n < 8; n++) {
            float2 x0 = up2(acc0[n][0]), x1 = up2(acc0[n][1]);
            float* p = sP0 + n * 132 + hh * 33 + dd;
            p[0] = x0.x; p[1] = x0.y; p[2] = x1.x; p[3] = x1.y;
            x0 = up2(acc1[n][0]); x1 = up2(acc1[n][1]);
            p = sP1 + n * 132 + hh * 33 + dd;
            p[0] = x0.x; p[1] = x0.y; p[2] = x1.x; p[3] = x1.y;
        }
    }
    __syncwarp();

    // ---------------- Phase E: GAT attention + reduction ----------------
    const int h = l >> 3, n = l & 7;
    const int gb = l & 24;
    #pragma unroll
    for (int r = 0; r < 2; r++) {
        const float* hp = r ? sP1 : sP0;
        const float* wd = r ? sW1 : sW0;
        const float* ad = r ? sA1 : sA0;

        float ei = 0.f, ej = 0.f;
        #pragma unroll
        for (int d = 0; d < 32; d++) {
            float v = hp[n * 132 + h * 33 + d];
            ei = fmaf(v, __ldg(attA + h * 64 + d), ei);
            ej = fmaf(v, __ldg(attA + h * 64 + 32 + d), ej);
        }
        float e[8];
        float mx = -3.4e38f;
        #pragma unroll
        for (int j = 0; j < 8; j++) {
            float t = ei + __shfl_sync(0xffffffffu, ej, gb + j);
            t = (t > 0.f) ? t : 0.2f * t;   // leaky relu
            e[j] = t;
            mx = fmaxf(mx, t);
        }
        float ssum = 0.f;
        #pragma unroll
        for (int j = 0; j < 8; j++) { e[j] = __expf(e[j] - mx); ssum += e[j]; }
        float inv = 1.f / ssum;

        float acc = 0.f;
        #pragma unroll
        for (int d = 0; d < 32; d++) {
            float g = 0.f;
            #pragma unroll
            for (int j = 0; j < 8; j++) g = fmaf(e[j], hp[j * 132 + h * 33 + d], g);
            g *= inv;                                  // softmax-normalized
            g = (g > 0.f) ? g : (__expf(g) - 1.f);     // elu
            acc = fmaf(wd[h * 33 + d], g, acc);
        }
        float wv = fabsf(acc);
        wv += __shfl_xor_sync(0xffffffffu, wv, 8);
        wv += __shfl_xor_sync(0xffffffffu, wv, 16);    // sum over heads (x4 dup per n)
        float t = ad[n] * (0.25f * wv - 1.f);
        #pragma unroll
        for (int off = 16; off >= 1; off >>= 1) t += __shfl_xor_sync(0xffffffffu, t, off);
        if (l == 0 && (r == 0 || v1)) out[r ? r1 : r0] = 0.25f * t;
    }
}

extern "C" void kernel_launch(void* const* d_in, const int* in_sizes, int n_in,
                              void* d_out, int out_size)
{
    const float* Qv   = (const float*)d_in[0];   // agent_qs
    const float* S    = (const float*)d_in[1];   // states
    const float* MQ   = (const float*)d_in[2];   // max_q_i
    const float* H    = (const float*)d_in[3];   // hidden_states
    const float* w1f  = (const float*)d_in[4];
    const float* b1f  = (const float*)d_in[5];
    const float* w2f  = (const float*)d_in[6];
    const float* b2f  = (const float*)d_in[7];
    // d_in[8..11] = w1v,b1v,w2v,b2v : algebraically cancel in adv_q, unused
    const float* Wg   = (const float*)d_in[12];
    const float* attA = (const float*)d_in[13];
    const float* Wd   = (const float*)d_in[14];
    const float* bd   = (const float*)d_in[15];

    int B = in_sizes[0] / 8;                      // bs*T rows
    int rowsPerBlock = NWARPS * 2;
    int grid = (B + rowsPerBlock - 1) / rowsPerBlock;
    size_t smem = (size_t)NWARPS * WARP_FLOATS * sizeof(float);

    cudaFuncSetAttribute(dvd_kernel, cudaFuncAttributeMaxDynamicSharedMemorySize, (int)smem);
    dvd_kernel<<<grid, NWARPS * 32, smem>>>((float*)d_out, Qv, S, MQ, H,
                                            w1f, b1f, w2f, b2f, Wg, attA, Wd, bd, B);
}

// round 2
// speedup vs baseline: 2.9411x; 2.9411x over previous
#include <cuda_runtime.h>

typedef unsigned long long ull;

#define NWARPS 4
// per-warp smem floats (total 1920):
//  sS0 @0 (168)  sS1 @168 (168)
//  sT0 @336 (640, H transposed, stride 10: [i*10+n])   } dead after Phase D
//  sT1 @976 (640)                                      }
//  hpb @0 (1152)  -- single-row hp buffer, ALIASES sS/sT (used only in E)
//  wd0 @1616 (144, [h*36+d])  wd1 @1760 (144)
//  adv0 @1904 (8)  adv1 @1912 (8)
#define WARP_FLOATS 1920

__device__ __forceinline__ ull pk2(float x, float y) {
    ull r; asm("mov.b64 %0, {%1, %2};" : "=l"(r) : "f"(x), "f"(y)); return r;
}
__device__ __forceinline__ ull dup2(float x) {
    ull r; asm("mov.b64 %0, {%1, %1};" : "=l"(r) : "f"(x)); return r;
}
__device__ __forceinline__ void fma2(ull& d, ull a, ull b) {
    asm("fma.rn.f32x2 %0, %1, %2, %0;" : "+l"(d) : "l"(a), "l"(b));
}
__device__ __forceinline__ float2 up2(ull v) {
    float2 f; asm("mov.b64 {%0, %1}, %2;" : "=f"(f.x), "=f"(f.y) : "l"(v)); return f;
}

// Store one row's hp accumulators (pair-over-n layout) into the smem buffer.
#define STORE_HP(ACC)                                                          \
    _Pragma("unroll")                                                          \
    for (int cc = 0; cc < 4; cc++) {                                           \
        _Pragma("unroll")                                                      \
        for (int np = 0; np < 4; np++) {                                       \
            float2 v = up2(ACC[cc][np]);                                       \
            hpb[((2 * np) * 4 + hh) * 36 + dd + cc]     = v.x;                 \
            hpb[((2 * np + 1) * 4 + hh) * 36 + dd + cc] = v.y;                 \
        }                                                                      \
    }

// Full per-row attention + reduction. Thread = (head hh, agent nn).
#define E_BODY(WDP, ADVP, OUTIDX, DOWRITE) {                                   \
    float ei = 0.f, ej = 0.f;                                                  \
    const float* myhp = hpb + (nn * 4 + hh) * 36;                              \
    _Pragma("unroll")                                                          \
    for (int dc = 0; dc < 8; dc++) {                                           \
        float4 v  = *(const float4*)(myhp + 4 * dc);                           \
        float4 a1 = __ldg((const float4*)(attA + hh * 64 + 4 * dc));           \
        float4 a2 = __ldg((const float4*)(attA + hh * 64 + 32 + 4 * dc));      \
        ei = fmaf(v.x, a1.x, ei); ei = fmaf(v.y, a1.y, ei);                    \
        ei = fmaf(v.z, a1.z, ei); ei = fmaf(v.w, a1.w, ei);                    \
        ej = fmaf(v.x, a2.x, ej); ej = fmaf(v.y, a2.y, ej);                    \
        ej = fmaf(v.z, a2.z, ej); ej = fmaf(v.w, a2.w, ej);                    \
    }                                                                          \
    float e[8]; float mx = -3.4e38f;                                           \
    _Pragma("unroll")                                                          \
    for (int j = 0; j < 8; j++) {                                              \
        float t = ei + __shfl_sync(0xffffffffu, ej, gb + j);                   \
        t = (t > 0.f) ? t : 0.2f * t;                                          \
        e[j] = t; mx = fmaxf(mx, t);                                           \
    }                                                                          \
    float ssum = 0.f;                                                          \
    _Pragma("unroll")                                                          \
    for (int j = 0; j < 8; j++) { e[j] = __expf(e[j] - mx); ssum += e[j]; }    \
    float inv = 1.f / ssum;                                                    \
    float acc = 0.f;                                                           \
    _Pragma("unroll")                                                          \
    for (int dc = 0; dc < 8; dc++) {                                           \
        float gx = 0.f, gy = 0.f, gz = 0.f, gw = 0.f;                          \
        _Pragma("unroll")                                                      \
        for (int j = 0; j < 8; j++) {                                          \
            float4 hv = *(const float4*)(hpb + (j * 4 + hh) * 36 + 4 * dc);    \
            gx = fmaf(e[j], hv.x, gx); gy = fmaf(e[j], hv.y, gy);              \
            gz = fmaf(e[j], hv.z, gz); gw = fmaf(e[j], hv.w, gw);              \
        }                                                                      \
        gx *= inv; gy *= inv; gz *= inv; gw *= inv;                            \
        gx = (gx > 0.f) ? gx : (__expf(gx) - 1.f);                             \
        gy = (gy > 0.f) ? gy : (__expf(gy) - 1.f);                             \
        gz = (gz > 0.f) ? gz : (__expf(gz) - 1.f);                             \
        gw = (gw > 0.f) ? gw : (__expf(gw) - 1.f);                             \
        float4 w4 = *(const float4*)(WDP + hh * 36 + 4 * dc);                  \
        acc = fmaf(w4.x, gx, acc); acc = fmaf(w4.y, gy, acc);                  \
        acc = fmaf(w4.z, gz, acc); acc = fmaf(w4.w, gw, acc);                  \
    }                                                                          \
    float wv = fabsf(acc);                                                     \
    wv += __shfl_xor_sync(0xffffffffu, wv, 8);                                 \
    wv += __shfl_xor_sync(0xffffffffu, wv, 16);                                \
    float t2 = ADVP[nn] * (0.25f * wv - 1.f);                                  \
    _Pragma("unroll")                                                          \
    for (int off = 16; off >= 1; off >>= 1)                                    \
        t2 += __shfl_xor_sync(0xffffffffu, t2, off);                           \
    if (l == 0 && (DOWRITE)) out[OUTIDX] = 0.25f * t2;                         \
}

__global__ void __launch_bounds__(NWARPS * 32, 4)
dvd_kernel(float* __restrict__ out,
           const float* __restrict__ Qv,  const float* __restrict__ Sg,
           const float* __restrict__ MQ,  const float* __restrict__ Hg,
           const float* __restrict__ w1f, const float* __restrict__ b1f,
           const float* __restrict__ w2f, const float* __restrict__ b2f,
           const float* __restrict__ Wg,  const float* __restrict__ attA,
           const float* __restrict__ Wd,  const float* __restrict__ bd,
           int B)
{
    extern __shared__ float sm[];
    const int l  = threadIdx.x & 31;
    const int wz = threadIdx.x >> 5;
    float* wb = sm + wz * WARP_FLOATS;

    const int base = (blockIdx.x * NWARPS + wz) * 2;
    if (base >= B) return;
    const int r0  = base;
    const bool v1 = (base + 1) < B;
    const int r1  = v1 ? (base + 1) : r0;

    float* sS0 = wb;          float* sS1 = wb + 168;
    float* sT0 = wb + 336;    float* sT1 = wb + 976;
    float* hpb = wb;          // aliases sS/sT; only used in Phase E
    float* wd0 = wb + 1616;   float* wd1 = wb + 1760;
    float* sA0 = wb + 1904;   float* sA1 = wb + 1912;

    // ---------------- Phase A: stage S and transposed H (stride 10) -------
    {
        const float* s0p = Sg + (size_t)r0 * 168;
        const float* s1p = Sg + (size_t)r1 * 168;
        for (int t = l; t < 168; t += 32) { sS0[t] = s0p[t]; sS1[t] = s1p[t]; }
        const float* h0p = Hg + (size_t)r0 * 512;
        const float* h1p = Hg + (size_t)r1 * 512;
        #pragma unroll
        for (int c = 0; c < 16; c++) {
            int t = c * 32 + l;
            int n = t >> 6, i = t & 63;
            sT0[i * 10 + n] = h0p[t];
            sT1[i * 10 + n] = h1p[t];
        }
    }
    __syncwarp();

    // ---------------- Phase B: w_final & adv_q (v-branch cancels) ---------
    {
        ull a0 = pk2(b1f[2 * l], b1f[2 * l + 1]);
        ull a1 = a0;
        #pragma unroll 2
        for (int k = 0; k < 168; k += 4) {
            float4 s0 = *(const float4*)(sS0 + k);
            float4 s1 = *(const float4*)(sS1 + k);
            float s0a[4] = {s0.x, s0.y, s0.z, s0.w};
            float s1a[4] = {s1.x, s1.y, s1.z, s1.w};
            #pragma unroll
            for (int m = 0; m < 4; m++) {
                float2 wv = *reinterpret_cast<const float2*>(w1f + (k + m) * 64 + 2 * l);
                ull wp = pk2(wv.x, wv.y);
                fma2(a0, dup2(s0a[m]), wp);
                fma2(a1, dup2(s1a[m]), wp);
            }
        }
        float2 f0 = up2(a0), f1 = up2(a1);
        f0.x = fmaxf(f0.x, 0.f); f0.y = fmaxf(f0.y, 0.f);
        f1.x = fmaxf(f1.x, 0.f); f1.y = fmaxf(f1.y, 0.f);

        float4 wa0 = __ldg((const float4*)(w2f + (2 * l) * 8));
        float4 wa1 = __ldg((const float4*)(w2f + (2 * l) * 8 + 4));
        float4 wb0 = __ldg((const float4*)(w2f + (2 * l + 1) * 8));
        float4 wb1 = __ldg((const float4*)(w2f + (2 * l + 1) * 8 + 4));
        float wa[8]  = {wa0.x, wa0.y, wa0.z, wa0.w, wa1.x, wa1.y, wa1.z, wa1.w};
        float wbv[8] = {wb0.x, wb0.y, wb0.z, wb0.w, wb1.x, wb1.y, wb1.z, wb1.w};

        float p0[8], p1[8];
        #pragma unroll
        for (int a = 0; a < 8; a++) {
            p0[a] = f0.x * wa[a] + f0.y * wbv[a];
            p1[a] = f1.x * wa[a] + f1.y * wbv[a];
        }
        #pragma unroll
        for (int off = 16; off >= 1; off >>= 1) {
            #pragma unroll
            for (int a = 0; a < 8; a++) {
                p0[a] += __shfl_xor_sync(0xffffffffu, p0[a], off);
                p1[a] += __shfl_xor_sync(0xffffffffu, p1[a], off);
            }
        }
        if (l == 0) {
            float4 qa = __ldg((const float4*)(Qv + (size_t)r0 * 8));
            float4 qb = __ldg((const float4*)(Qv + (size_t)r0 * 8 + 4));
            float4 ma = __ldg((const float4*)(MQ + (size_t)r0 * 8));
            float4 mb = __ldg((const float4*)(MQ + (size_t)r0 * 8 + 4));
            float qd[8] = {qa.x - ma.x, qa.y - ma.y, qa.z - ma.z, qa.w - ma.w,
                           qb.x - mb.x, qb.y - mb.y, qb.z - mb.z, qb.w - mb.w};
            #pragma unroll
            for (int a = 0; a < 8; a++)
                sA0[a] = (fabsf(p0[a] + b2f[a]) + 1e-10f) * qd[a];
            float4 qa1 = __ldg((const float4*)(Qv + (size_t)r1 * 8));
            float4 qb1 = __ldg((const float4*)(Qv + (size_t)r1 * 8 + 4));
            float4 ma1 = __ldg((const float4*)(MQ + (size_t)r1 * 8));
            float4 mb1 = __ldg((const float4*)(MQ + (size_t)r1 * 8 + 4));
            float qd1[8] = {qa1.x - ma1.x, qa1.y - ma1.y, qa1.z - ma1.z, qa1.w - ma1.w,
                            qb1.x - mb1.x, qb1.y - mb1.y, qb1.z - mb1.z, qb1.w - mb1.w};
            #pragma unroll
            for (int a = 0; a < 8; a++)
                sA1[a] = (fabsf(p1[a] + b2f[a]) + 1e-10f) * qd1[a];
        }
    }

    const int hh = l >> 3, nn = l & 7, gb = l & 24, dd = 4 * (l & 7);

    // ---------------- Phase C: w_dvd = S@Wd + bd --------------------------
    {
        float4 b4 = __ldg((const float4*)(bd + 4 * l));
        ull c00 = pk2(b4.x, b4.y), c01 = pk2(b4.z, b4.w);
        ull c10 = c00, c11 = c01;
        #pragma unroll 2
        for (int k = 0; k < 168; k += 4) {
            float4 s0 = *(const float4*)(sS0 + k);
            float4 s1 = *(const float4*)(sS1 + k);
            float s0a[4] = {s0.x, s0.y, s0.z, s0.w};
            float s1a[4] = {s1.x, s1.y, s1.z, s1.w};
            #pragma unroll
            for (int m = 0; m < 4; m++) {
                float4 wv = __ldg((const float4*)(Wd + (k + m) * 128 + 4 * l));
                ull wp0 = pk2(wv.x, wv.y), wp1 = pk2(wv.z, wv.w);
                ull d0 = dup2(s0a[m]), d1 = dup2(s1a[m]);
                fma2(c00, d0, wp0); fma2(c01, d0, wp1);
                fma2(c10, d1, wp0); fma2(c11, d1, wp1);
            }
        }
        float2 x0 = up2(c00), x1 = up2(c01);
        *(float4*)(wd0 + hh * 36 + dd) = make_float4(x0.x, x0.y, x1.x, x1.y);
        x0 = up2(c10); x1 = up2(c11);
        *(float4*)(wd1 + hh * 36 + dd) = make_float4(x0.x, x0.y, x1.x, x1.y);
    }

    // ---------------- Phase D: hp = H @ Wg, pair-over-n accumulation ------
    ull acc0[4][4], acc1[4][4];   // [cc][np]: {hp[2np, 4l+cc], hp[2np+1, 4l+cc]}
    #pragma unroll
    for (int cc = 0; cc < 4; cc++)
        #pragma unroll
        for (int np = 0; np < 4; np++) { acc0[cc][np] = 0ull; acc1[cc][np] = 0ull; }

    #pragma unroll 4
    for (int i = 0; i < 64; i++) {
        float4 wg = __ldg((const float4*)(Wg + i * 128 + 4 * l));
        ull w0 = dup2(wg.x), w1 = dup2(wg.y), w2 = dup2(wg.z), w3 = dup2(wg.w);
        #pragma unroll
        for (int np = 0; np < 4; np++) {
            ull h0 = *(const ull*)(sT0 + i * 10 + 2 * np);
            fma2(acc0[0][np], h0, w0); fma2(acc0[1][np], h0, w1);
            fma2(acc0[2][np], h0, w2); fma2(acc0[3][np], h0, w3);
            ull h1 = *(const ull*)(sT1 + i * 10 + 2 * np);
            fma2(acc1[0][np], h1, w0); fma2(acc1[1][np], h1, w1);
            fma2(acc1[2][np], h1, w2); fma2(acc1[3][np], h1, w3);
        }
    }

    // ---------------- Phase E: attention + reduction, one row at a time ---
    __syncwarp();                 // all lanes done reading sS/sT before alias
    STORE_HP(acc0);
    __syncwarp();
    E_BODY(wd0, sA0, r0, true);
    __syncwarp();                 // all lanes done reading row0 hp
    STORE_HP(acc1);
    __syncwarp();
    E_BODY(wd1, sA1, r1, v1);
}

extern "C" void kernel_launch(void* const* d_in, const int* in_sizes, int n_in,
                              void* d_out, int out_size)
{
    const float* Qv   = (const float*)d_in[0];   // agent_qs
    const float* S    = (const float*)d_in[1];   // states
    const float* MQ   = (const float*)d_in[2];   // max_q_i
    const float* H    = (const float*)d_in[3];   // hidden_states
    const float* w1f  = (const float*)d_in[4];
    const float* b1f  = (const float*)d_in[5];
    const float* w2f  = (const float*)d_in[6];
    const float* b2f  = (const float*)d_in[7];
    // d_in[8..11] = w1v,b1v,w2v,b2v : cancel algebraically in adv_q, unused
    const float* Wg   = (const float*)d_in[12];
    const float* attA = (const float*)d_in[13];
    const float* Wd   = (const float*)d_in[14];
    const float* bd   = (const float*)d_in[15];

    int B = in_sizes[0] / 8;                      // bs*T rows
    int rowsPerBlock = NWARPS * 2;
    int grid = (B + rowsPerBlock - 1) / rowsPerBlock;
    size_t smem = (size_t)NWARPS * WARP_FLOATS * sizeof(float);

    dvd_kernel<<<grid, NWARPS * 32, smem>>>((float*)d_out, Qv, S, MQ, H,
                                            w1f, b1f, w2f, b2f, Wg, attA, Wd, bd, B);
}

// round 3
// speedup vs baseline: 3.3122x; 1.1262x over previous
#include <cuda_runtime.h>

typedef unsigned long long ull;

#define NWARPS 4
// per-warp smem floats (2848):
//  sS  @0    (672  = 4*168)            per-row S
//  sT  @672  (1536 = 2*768, H^T stride 12)  [aliased by sh1 (4*68) in Phase B tail]
//  swd @2208 (592  = 4*148)  [r][h*36+d]
//  sA  @2800 (48   = 4*12)   [r][0..7]=adv, [r][8]=sum(adv)
#define WARP_FLOATS 2848

__device__ __forceinline__ ull pk2(float x, float y) {
    ull r; asm("mov.b64 %0, {%1, %2};" : "=l"(r) : "f"(x), "f"(y)); return r;
}
__device__ __forceinline__ ull dup2(float x) {
    ull r; asm("mov.b64 %0, {%1, %1};" : "=l"(r) : "f"(x)); return r;
}
__device__ __forceinline__ void fma2(ull& d, ull a, ull b) {
    asm("fma.rn.f32x2 %0, %1, %2, %0;" : "+l"(d) : "l"(a), "l"(b));
}
__device__ __forceinline__ ull add2(ull a, ull b) {
    ull r; asm("add.rn.f32x2 %0, %1, %2;" : "=l"(r) : "l"(a), "l"(b)); return r;
}
__device__ __forceinline__ float2 up2(ull v) {
    float2 f; asm("mov.b64 {%0, %1}, %2;" : "=f"(f.x), "=f"(f.y) : "l"(v)); return f;
}

// Fully register/shfl-based GAT attention + final reduction for one row.
// acc[cc][np] = {hp[n=2np][col], hp[n=2np+1][col]}, col = 4*l+cc.
// lane l: h = l>>3, dc = l&7 (owns d-range 4dc..4dc+3 of head h, all 8 agents).
__device__ __forceinline__ void phaseE(const ull acc[4][4],
                                       const float* __restrict__ swdR,
                                       const float* __restrict__ sAR,
                                       float4 a1, float4 a2, int l,
                                       float* __restrict__ out, int rowIdx, bool valid)
{
    const int hh = l >> 3, dc = l & 7, gb = l & 24;
    const float a1c[4] = {a1.x, a1.y, a1.z, a1.w};
    const float a2c[4] = {a2.x, a2.y, a2.z, a2.w};

    // 1) partial e_i / e_j dots over this lane's 4 d's, all 8 agents (as pairs)
    ull eip[4], ejp[4];
    #pragma unroll
    for (int np = 0; np < 4; np++) { eip[np] = 0ull; ejp[np] = 0ull; }
    #pragma unroll
    for (int cc = 0; cc < 4; cc++) {
        ull ai = dup2(a1c[cc]), aj = dup2(a2c[cc]);
        #pragma unroll
        for (int np = 0; np < 4; np++) {
            fma2(eip[np], ai, acc[cc][np]);
            fma2(ejp[np], aj, acc[cc][np]);
        }
    }
    // 2) reduce partials across the 8-lane h-group
    #pragma unroll
    for (int off = 1; off < 8; off <<= 1) {
        #pragma unroll
        for (int np = 0; np < 4; np++) {
            eip[np] = add2(eip[np], __shfl_xor_sync(0xffffffffu, eip[np], off));
            ejp[np] = add2(ejp[np], __shfl_xor_sync(0xffffffffu, ejp[np], off));
        }
    }
    float ei[8], ej[8];
    #pragma unroll
    for (int np = 0; np < 4; np++) {
        float2 t = up2(eip[np]); ei[2*np] = t.x; ei[2*np+1] = t.y;
        float2 u = up2(ejp[np]); ej[2*np] = u.x; ej[2*np+1] = u.y;
    }
    // 3) softmax of attention row i = dc (each lane owns one i)
    float eii = (dc & 4) ? ((dc & 2) ? ((dc & 1) ? ei[7] : ei[6]) : ((dc & 1) ? ei[5] : ei[4]))
                         : ((dc & 2) ? ((dc & 1) ? ei[3] : ei[2]) : ((dc & 1) ? ei[1] : ei[0]));
    float e[8], mx = -3.4e38f;
    #pragma unroll
    for (int j = 0; j < 8; j++) {
        float t = eii + ej[j];
        t = fmaxf(t, 0.2f * t);          // leaky relu (slope 0.2)
        e[j] = t; mx = fmaxf(mx, t);
    }
    float ssum = 0.f;
    #pragma unroll
    for (int j = 0; j < 8; j++) { e[j] = __expf(e[j] - mx); ssum += e[j]; }
    float inv = 1.f / ssum;
    #pragma unroll
    for (int j = 0; j < 8; j++) e[j] *= inv;
    ull anp[4];
    #pragma unroll
    for (int np = 0; np < 4; np++) anp[np] = pk2(e[2*np], e[2*np+1]);

    // 4) per-i weighted sums (attn rows broadcast by shfl), elu, w_dvd dot partial
    float4 wd4 = *(const float4*)(swdR + hh * 36 + 4 * dc);
    const float wdc[4] = {wd4.x, wd4.y, wd4.z, wd4.w};
    float wp[8];
    #pragma unroll
    for (int ip = 0; ip < 8; ip++) {
        int src = gb + ip;
        ull ap0 = __shfl_sync(0xffffffffu, anp[0], src);
        ull ap1 = __shfl_sync(0xffffffffu, anp[1], src);
        ull ap2 = __shfl_sync(0xffffffffu, anp[2], src);
        ull ap3 = __shfl_sync(0xffffffffu, anp[3], src);
        float accw = 0.f;
        #pragma unroll
        for (int cc = 0; cc < 4; cc++) {
            ull g2 = 0ull;
            fma2(g2, ap0, acc[cc][0]);
            fma2(g2, ap1, acc[cc][1]);
            fma2(g2, ap2, acc[cc][2]);
            fma2(g2, ap3, acc[cc][3]);
            float2 gh = up2(g2);
            float g = gh.x + gh.y;
            g = (g > 0.f) ? g : (__expf(g) - 1.f);   // elu
            accw = fmaf(wdc[cc], g, accw);
        }
        wp[ip] = accw;
    }
    // 5) complete d-sums across h-group, then adv reduction
    #pragma unroll
    for (int off = 1; off < 8; off <<= 1)
        #pragma unroll
        for (int ip = 0; ip < 8; ip++)
            wp[ip] += __shfl_xor_sync(0xffffffffu, wp[ip], off);

    float4 ad0 = *(const float4*)(sAR);
    float4 ad1 = *(const float4*)(sAR + 4);
    float advsum = sAR[8];
    const float adc[8] = {ad0.x, ad0.y, ad0.z, ad0.w, ad1.x, ad1.y, ad1.z, ad1.w};
    float p = 0.f;
    #pragma unroll
    for (int ip = 0; ip < 8; ip++) p = fmaf(adc[ip], fabsf(wp[ip]), p);
    p += __shfl_xor_sync(0xffffffffu, p, 8);
    p += __shfl_xor_sync(0xffffffffu, p, 16);      // sum over 4 heads
    if (l == 0 && valid) out[rowIdx] = 0.25f * p - advsum;
}

__global__ void __launch_bounds__(NWARPS * 32, 4)
dvd_kernel(float* __restrict__ out,
           const float* __restrict__ Qv,  const float* __restrict__ Sg,
           const float* __restrict__ MQ,  const float* __restrict__ Hg,
           const float* __restrict__ w1f, const float* __restrict__ b1f,
           const float* __restrict__ w2f, const float* __restrict__ b2f,
           const float* __restrict__ Wg,  const float* __restrict__ attA,
           const float* __restrict__ Wd,  const float* __restrict__ bd,
           int B)
{
    extern __shared__ float sm[];
    const int l  = threadIdx.x & 31;
    const int wz = threadIdx.x >> 5;
    float* wb = sm + wz * WARP_FLOATS;

    const int base = (blockIdx.x * NWARPS + wz) * 4;
    if (base >= B) return;
    const int Bm1 = B - 1;
    int rr[4]; bool vv[4];
    #pragma unroll
    for (int r = 0; r < 4; r++) { int x = base + r; vv[r] = x < B; rr[r] = vv[r] ? x : Bm1; }

    float* sS  = wb;
    float* sT0 = wb + 672;
    float* sT1 = wb + 672 + 768;
    float* sh1 = wb + 672;          // aliases sT (Phase B tail only)
    float* swd = wb + 2208;
    float* sA  = wb + 2800;

    // ---------------- Phase A: stage S (4 rows) ----------------
    #pragma unroll
    for (int r = 0; r < 4; r++) {
        const float* sp = Sg + (size_t)rr[r] * 168;
        for (int t = l; t < 168; t += 32) sS[r * 168 + t] = sp[t];
    }
    __syncwarp();

    // ---------------- Phase B: w_final & adv (v-branch cancels) ----------
    {
        ull a[4];
        {
            float2 b2 = *(const float2*)(b1f + 2 * l);
            ull binit = pk2(b2.x, b2.y);
            #pragma unroll
            for (int r = 0; r < 4; r++) a[r] = binit;
        }
        #pragma unroll 2
        for (int k = 0; k < 168; k += 4) {
            float sv[4][4];
            #pragma unroll
            for (int r = 0; r < 4; r++) {
                float4 s4 = *(const float4*)(sS + r * 168 + k);
                sv[r][0] = s4.x; sv[r][1] = s4.y; sv[r][2] = s4.z; sv[r][3] = s4.w;
            }
            #pragma unroll
            for (int m = 0; m < 4; m++) {
                float2 wv = *(const float2*)(w1f + (k + m) * 64 + 2 * l);
                ull wpk = pk2(wv.x, wv.y);
                #pragma unroll
                for (int r = 0; r < 4; r++) fma2(a[r], dup2(sv[r][m]), wpk);
            }
        }
        #pragma unroll
        for (int r = 0; r < 4; r++) {
            float2 f = up2(a[r]);
            *(float2*)(sh1 + r * 68 + 2 * l) = make_float2(fmaxf(f.x, 0.f), fmaxf(f.y, 0.f));
        }
        __syncwarp();
        // second layer: lane = (row = l>>3, agent = l&7)
        const int r = l >> 3, aa = l & 7;
        float acc2 = __ldg(b2f + aa);
        #pragma unroll 4
        for (int k = 0; k < 64; k += 4) {
            float4 h4 = *(const float4*)(sh1 + r * 68 + k);
            acc2 = fmaf(h4.x, __ldg(w2f + (k    ) * 8 + aa), acc2);
            acc2 = fmaf(h4.y, __ldg(w2f + (k + 1) * 8 + aa), acc2);
            acc2 = fmaf(h4.z, __ldg(w2f + (k + 2) * 8 + aa), acc2);
            acc2 = fmaf(h4.w, __ldg(w2f + (k + 3) * 8 + aa), acc2);
        }
        float wf = fabsf(acc2) + 1e-10f;
        int rg = rr[r];
        float adv = wf * (__ldg(Qv + (size_t)rg * 8 + aa) - __ldg(MQ + (size_t)rg * 8 + aa));
        float asum = adv;
        asum += __shfl_xor_sync(0xffffffffu, asum, 1);
        asum += __shfl_xor_sync(0xffffffffu, asum, 2);
        asum += __shfl_xor_sync(0xffffffffu, asum, 4);
        sA[r * 12 + aa] = adv;
        if (aa == 0) sA[r * 12 + 8] = asum;
        __syncwarp();
    }

    // ---------------- Phase C: w_dvd = S@Wd + bd (4 rows) ----------------
    {
        float4 b4 = __ldg((const float4*)(bd + 4 * l));
        ull cA[4][2];
        #pragma unroll
        for (int r = 0; r < 4; r++) { cA[r][0] = pk2(b4.x, b4.y); cA[r][1] = pk2(b4.z, b4.w); }
        #pragma unroll 2
        for (int k = 0; k < 168; k += 4) {
            float sv[4][4];
            #pragma unroll
            for (int r = 0; r < 4; r++) {
                float4 s4 = *(const float4*)(sS + r * 168 + k);
                sv[r][0] = s4.x; sv[r][1] = s4.y; sv[r][2] = s4.z; sv[r][3] = s4.w;
            }
            #pragma unroll
            for (int m = 0; m < 4; m++) {
                float4 wv = __ldg((const float4*)(Wd + (k + m) * 128 + 4 * l));
                ull wp0 = pk2(wv.x, wv.y), wp1 = pk2(wv.z, wv.w);
                #pragma unroll
                for (int r = 0; r < 4; r++) {
                    ull d = dup2(sv[r][m]);
                    fma2(cA[r][0], d, wp0); fma2(cA[r][1], d, wp1);
                }
            }
        }
        const int hh = l >> 3, dd = 4 * (l & 7);
        #pragma unroll
        for (int r = 0; r < 4; r++) {
            float2 x0 = up2(cA[r][0]), x1 = up2(cA[r][1]);
            *(float4*)(swd + r * 148 + hh * 36 + dd) = make_float4(x0.x, x0.y, x1.x, x1.y);
        }
        __syncwarp();
    }

    // attA coefficients for this lane (reused for all 4 rows)
    const int hE = l >> 3, dE = l & 7;
    float4 a1 = __ldg((const float4*)(attA + hE * 64 + 4 * dE));
    float4 a2 = __ldg((const float4*)(attA + hE * 64 + 32 + 4 * dE));

    // ---------------- Phases D+E: two passes of 2 rows -------------------
    #pragma unroll
    for (int pass = 0; pass < 2; pass++) {
        const int i0 = 2 * pass, i1 = 2 * pass + 1;
        __syncwarp();
        {   // stage H^T (stride 12) for the 2 rows of this pass
            const float* h0p = Hg + (size_t)rr[i0] * 512;
            const float* h1p = Hg + (size_t)rr[i1] * 512;
            #pragma unroll
            for (int c = 0; c < 16; c++) {
                int t = c * 32 + l;
                int n = t >> 6, i = t & 63;
                sT0[i * 12 + n] = h0p[t];
                sT1[i * 12 + n] = h1p[t];
            }
        }
        __syncwarp();

        ull acc0[4][4], acc1[4][4];
        #pragma unroll
        for (int cc = 0; cc < 4; cc++)
            #pragma unroll
            for (int np = 0; np < 4; np++) { acc0[cc][np] = 0ull; acc1[cc][np] = 0ull; }

        #pragma unroll 4
        for (int i = 0; i < 64; i++) {
            float4 wg = __ldg((const float4*)(Wg + i * 128 + 4 * l));
            ull w0 = dup2(wg.x), w1 = dup2(wg.y), w2 = dup2(wg.z), w3 = dup2(wg.w);
            float4 hA0 = *(const float4*)(sT0 + i * 12);
            float4 hA1 = *(const float4*)(sT0 + i * 12 + 4);
            float4 hB0 = *(const float4*)(sT1 + i * 12);
            float4 hB1 = *(const float4*)(sT1 + i * 12 + 4);
            ull pA[4] = {pk2(hA0.x, hA0.y), pk2(hA0.z, hA0.w), pk2(hA1.x, hA1.y), pk2(hA1.z, hA1.w)};
            ull pB[4] = {pk2(hB0.x, hB0.y), pk2(hB0.z, hB0.w), pk2(hB1.x, hB1.y), pk2(hB1.z, hB1.w)};
            #pragma unroll
            for (int np = 0; np < 4; np++) {
                fma2(acc0[0][np], pA[np], w0); fma2(acc0[1][np], pA[np], w1);
                fma2(acc0[2][np], pA[np], w2); fma2(acc0[3][np], pA[np], w3);
                fma2(acc1[0][np], pB[np], w0); fma2(acc1[1][np], pB[np], w1);
                fma2(acc1[2][np], pB[np], w2); fma2(acc1[3][np], pB[np], w3);
            }
        }

        phaseE(acc0, swd + i0 * 148, sA + i0 * 12, a1, a2, l, out, base + i0, vv[i0]);
        phaseE(acc1, swd + i1 * 148, sA + i1 * 12, a1, a2, l, out, base + i1, vv[i1]);
    }
}

extern "C" void kernel_launch(void* const* d_in, const int* in_sizes, int n_in,
                              void* d_out, int out_size)
{
    const float* Qv   = (const float*)d_in[0];   // agent_qs
    const float* S    = (const float*)d_in[1];   // states
    const float* MQ   = (const float*)d_in[2];   // max_q_i
    const float* H    = (const float*)d_in[3];   // hidden_states
    const float* w1f  = (const float*)d_in[4];
    const float* b1f  = (const float*)d_in[5];
    const float* w2f  = (const float*)d_in[6];
    const float* b2f  = (const float*)d_in[7];
    // d_in[8..11] = w1v,b1v,w2v,b2v : cancel algebraically in adv_q, unused
    const float* Wg   = (const float*)d_in[12];
    const float* attA = (const float*)d_in[13];
    const float* Wd   = (const float*)d_in[14];
    const float* bd   = (const float*)d_in[15];

    int B = in_sizes[0] / 8;                      // bs*T rows
    int rowsPerBlock = NWARPS * 4;
    int grid = (B + rowsPerBlock - 1) / rowsPerBlock;
    size_t smem = (size_t)NWARPS * WARP_FLOATS * sizeof(float);

    dvd_kernel<<<grid, NWARPS * 32, smem>>>((float*)d_out, Qv, S, MQ, H,
                                            w1f, b1f, w2f, b2f, Wg, attA, Wd, bd, B);
}